// round 14
// baseline (speedup 1.0000x reference)
#include <cuda_runtime.h>
#include <cuda_fp16.h>
#include <cstdint>

#define H      512
#define SDIM   2048
#define BATCH  32
#define KDIM   1024      // 2*H
#define MTOT   65536     // BATCH*SDIM
#define M_TILE 128
#define N_TILE 128
#define K_TILE 64        // fp16 elems per k-tile = 128 B rows
#define NKT    16        // KDIM / K_TILE
#define NSTAGE 3
#define NSPLIT 4         // H / N_TILE
#define NTILES (MTOT / M_TILE)   // 512

// ---------------- scratch (device globals: allocation-free) ----------------
__device__ __half g_ench[(size_t)MTOT * KDIM];   // encoder_out in fp16 (128 MB)
__device__ __half g_Wth[H * KDIM];               // W_e^T [n][k] in fp16
__device__ float  g_dec[BATCH * H];              // dec_proj + b_attn (fp32 exact)
__device__ float  g_part[NSPLIT * MTOT];         // per-N-slice partial logits
__device__ int    g_flag[NTILES * 4];            // per-(m-tile, k-slice) ready flags

#define STAGE_BYTES 16384
#define B_BASE      (NSTAGE * STAGE_BYTES)
#define SMEM_TOTAL  (2 * NSTAGE * STAGE_BYTES)   // 96 KB

__device__ __forceinline__ uint32_t smem_u32(const void* p) {
    uint32_t a;
    asm("{ .reg .u64 t; cvta.to.shared.u64 t, %1; cvt.u32.u64 %0, t; }" : "=r"(a) : "l"(p));
    return a;
}
__device__ __forceinline__ uint32_t h2_bits(__half2 h) {
    return *reinterpret_cast<uint32_t*>(&h);
}
__device__ __forceinline__ void cp16(uint32_t dst, const void* src) {
    asm volatile("cp.async.cg.shared.global [%0], [%1], 16;" :: "r"(dst), "l"(src) : "memory");
}
__device__ __forceinline__ void ldsm4(uint32_t* r, uint32_t addr) {
    asm volatile("ldmatrix.sync.aligned.m8n8.x4.shared.b16 {%0,%1,%2,%3}, [%4];"
                 : "=r"(r[0]), "=r"(r[1]), "=r"(r[2]), "=r"(r[3]) : "r"(addr));
}
__device__ __forceinline__ void mma_f16(float* c, const uint32_t* a, uint32_t b0, uint32_t b1) {
    asm volatile(
        "mma.sync.aligned.m16n8k16.row.col.f32.f16.f16.f32 "
        "{%0,%1,%2,%3}, {%4,%5,%6,%7}, {%8,%9}, {%0,%1,%2,%3};"
        : "+f"(c[0]), "+f"(c[1]), "+f"(c[2]), "+f"(c[3])
        : "r"(a[0]), "r"(a[1]), "r"(a[2]), "r"(a[3]), "r"(b0), "r"(b1));
}

// ---------------- kernel 1: merged prep (W_e transpose + dec_proj) ---------
// blocks [0,512): W_e transpose + fp16 round + flag zeroing (32x16 tiling)
// blocks [512,1024): dec_proj = decoder_hide @ W_h + b_attn  (16x32 tiling)
__global__ void prep_all(const float* __restrict__ W,
                         const float* __restrict__ dh,
                         const float* __restrict__ bias) {
    int tx = threadIdx.x, ty = threadIdx.y;
    if (blockIdx.x < 512) {
        __shared__ float tile[32][33];
        int bx = blockIdx.x & 31, by = blockIdx.x >> 5;     // 32 x 16
        int kb = bx * 32, nb = by * 32;
        if (tx < 4 && ty == 0)
            g_flag[blockIdx.x * 4 + tx] = 0;                // 512 blocks x 4
        #pragma unroll
        for (int i = ty; i < 32; i += 8)
            tile[i][tx] = W[(size_t)(H + kb + i) * H + nb + tx];
        __syncthreads();
        #pragma unroll
        for (int i = ty; i < 32; i += 8)
            g_Wth[(size_t)(nb + i) * KDIM + kb + tx] = __float2half_rn(tile[tx][i]);
    } else {
        __shared__ float row[H];
        __shared__ float red[8][32];
        int bid = blockIdx.x - 512;
        int b = bid >> 4;                                    // 16 h-blocks per batch
        int h = (bid & 15) * 32 + tx;
        for (int i = ty * 32 + tx; i < H; i += 256) row[i] = dh[b * H + i];
        __syncthreads();
        float acc = 0.f;
        #pragma unroll 8
        for (int kk = 0; kk < 64; kk++) {
            int k = ty * 64 + kk;
            acc = fmaf(row[k], W[(size_t)k * H + h], acc);
        }
        red[ty][tx] = acc;
        __syncthreads();
        if (ty == 0) {
            float s = bias[h];
            #pragma unroll
            for (int j = 0; j < 8; j++) s += red[j][tx];
            g_dec[b * H + h] = s;
        }
    }
}

// ---------------- kernel 3: fused convert + fp16 GEMM + tanh + v_w reduce --
// grid (NSPLIT, NTILES). CTA (x,y) converts K-slice x of A tile y, publishes a
// flag, then runs the K-mainloop ROTATED to start at its own slice (kt = 4x).
// Prologue overlap: stage-0 B cp.asyncs (independent of conversion) are issued
// BEFORE the convert; group committed after the post-convert A loads.
__global__ void __launch_bounds__(256, 2)
gemm_kernel(const float* __restrict__ enc, const float* __restrict__ vw) {
    extern __shared__ char smem[];
    const uint32_t sbase = smem_u32(smem);
    const int tid = threadIdx.x, lid = tid & 31, wid = tid >> 5;
    const int wm = wid & 1, wn = wid >> 1;          // 2 x 4 warp grid
    const int m0 = blockIdx.y * M_TILE;
    const int nb = blockIdx.x * N_TILE;
    const int batch = blockIdx.y >> 4;              // 16 M-tiles per batch row
    const int xs = blockIdx.x;                      // this CTA's K-slice
    const int x4 = xs * 4;                          // first kt of own slice

    auto load_A = [&](int slot, int kt) {
        const __half* asrc = g_ench + (size_t)m0 * KDIM + kt * K_TILE;
        uint32_t abase = sbase + slot * STAGE_BYTES;
        #pragma unroll
        for (int i = 0; i < 4; i++) {
            int c = tid + i * 256;
            int row = c >> 3, cu = c & 7;
            cp16(abase + row * 128 + ((cu ^ (row & 7)) << 4),
                 asrc + (size_t)row * KDIM + cu * 8);
        }
    };
    auto load_B = [&](int slot, int kt) {
        const __half* bsrc = g_Wth + (size_t)nb * KDIM + kt * K_TILE;
        uint32_t bbase = sbase + B_BASE + slot * STAGE_BYTES;
        #pragma unroll
        for (int i = 0; i < 4; i++) {
            int c = tid + i * 256;
            int row = c >> 3, cu = c & 7;
            cp16(bbase + row * 128 + ((cu ^ (row & 7)) << 4),
                 bsrc + (size_t)row * KDIM + cu * 8);
        }
    };

    // ---- prologue: B0 loads fly under the conversion -----------------------
    load_B(0, x4);
    {
        const float4* s4 = (const float4*)(enc + (size_t)m0 * KDIM + xs * 256);
        uint2* d2 = (uint2*)(g_ench + (size_t)m0 * KDIM + xs * 256);
        #pragma unroll 8
        for (int j = 0; j < 32; j++) {               // 128 rows * 64 f4 / 256 thr
            int c = tid + j * 256;
            int r = c >> 6, c4 = c & 63;
            float4 f = s4[(size_t)r * 256 + c4];
            uint2 o;
            o.x = h2_bits(__floats2half2_rn(f.x, f.y));
            o.y = h2_bits(__floats2half2_rn(f.z, f.w));
            d2[(size_t)r * 256 + c4] = o;
        }
        __threadfence();
        __syncthreads();
        if (tid == 0)
            asm volatile("st.global.release.gpu.b32 [%0], %1;"
                         :: "l"(&g_flag[blockIdx.y * 4 + xs]), "r"(1) : "memory");
    }
    load_A(0, x4);
    asm volatile("cp.async.commit_group;" ::: "memory");
    load_B(1, (x4 + 1) & 15);
    load_A(1, (x4 + 1) & 15);
    asm volatile("cp.async.commit_group;" ::: "memory");

    const int s7 = lid & 7;
    const int rA = s7 + 8 * ((lid >> 3) & 1);       // A ldsm row-in-16
    const int cA = (lid >> 4) & 1;                  // A chunk parity (k8)
    const int rB = s7 + 8 * ((lid >> 4) & 1);       // B ldsm row-in-16
    const int cB = (lid >> 3) & 1;                  // B chunk parity

    float acc[4][4][4];
    #pragma unroll
    for (int mi = 0; mi < 4; mi++)
        #pragma unroll
        for (int ni = 0; ni < 4; ni++)
            #pragma unroll
            for (int q = 0; q < 4; q++) acc[mi][ni][q] = 0.f;

    auto wait_slice = [&](int s) {                   // all threads spin
        const int* fp = &g_flag[blockIdx.y * 4 + s];
        int v;
        do {
            asm volatile("ld.global.acquire.gpu.b32 %0, [%1];"
                         : "=r"(v) : "l"(fp) : "memory");
            if (!v) __nanosleep(50);
        } while (!v);
    };

    uint32_t aF[2][4][4], bF[2][2][4];

    for (int i = 0; i < NKT; ++i) {
        asm volatile("cp.async.wait_group 1;" ::: "memory");
        __syncthreads();
        if (i + 2 < NKT) {
            const int kta = (x4 + i + 2) & 15;
            if ((kta & 3) == 0 && (kta >> 2) != xs)  // entering a foreign slice
                wait_slice(kta >> 2);
            load_B((i + 2) % NSTAGE, kta);
            load_A((i + 2) % NSTAGE, kta);
        }
        asm volatile("cp.async.commit_group;" ::: "memory");

        const int slot = i % NSTAGE;
        const uint32_t As = sbase + slot * STAGE_BYTES;
        const uint32_t Bs = sbase + B_BASE + slot * STAGE_BYTES;
        uint32_t abA[4], abB[2];
        #pragma unroll
        for (int mi = 0; mi < 4; mi++)
            abA[mi] = As + (wm * 64 + mi * 16 + rA) * 128;
        #pragma unroll
        for (int p = 0; p < 2; p++)
            abB[p] = Bs + (wn * 32 + p * 16 + rB) * 128;

        {
            uint32_t chA = (uint32_t)((cA ^ s7) << 4);
            uint32_t chB = (uint32_t)((cB ^ s7) << 4);
            #pragma unroll
            for (int mi = 0; mi < 4; mi++) ldsm4(aF[0][mi], abA[mi] + chA);
            #pragma unroll
            for (int p = 0; p < 2; p++)    ldsm4(bF[0][p], abB[p] + chB);
        }

        #pragma unroll
        for (int g = 0; g < 4; g++) {                 // k16 groups in k-tile
            const int cur = g & 1, nxt = cur ^ 1;
            if (g < 3) {
                uint32_t chA = (uint32_t)(((2 * (g + 1) + cA) ^ s7) << 4);
                uint32_t chB = (uint32_t)(((2 * (g + 1) + cB) ^ s7) << 4);
                #pragma unroll
                for (int mi = 0; mi < 4; mi++) ldsm4(aF[nxt][mi], abA[mi] + chA);
                #pragma unroll
                for (int p = 0; p < 2; p++)    ldsm4(bF[nxt][p], abB[p] + chB);
            }
            #pragma unroll
            for (int mi = 0; mi < 4; mi++)
                #pragma unroll
                for (int ni = 0; ni < 4; ni++)
                    mma_f16(acc[mi][ni], aF[cur][mi],
                            bF[cur][ni >> 1][(ni & 1) * 2], bF[cur][ni >> 1][(ni & 1) * 2 + 1]);
        }
    }

    // ---------------- epilogue: tanh + v_w reduce across lanes AND wn warps --
    float decv[8], vwv[8];
    #pragma unroll
    for (int ni = 0; ni < 4; ni++)
        #pragma unroll
        for (int j = 0; j < 2; j++) {
            int h = nb + wn * 32 + ni * 8 + 2 * (lid & 3) + j;
            decv[ni * 2 + j] = g_dec[batch * H + h];
            vwv[ni * 2 + j]  = vw[h];
        }
    __syncthreads();                       // stages dead; reuse smem for reduce
    float* part_s = (float*)smem;          // [wn][128] = 2 KB
    #pragma unroll
    for (int mi = 0; mi < 4; mi++) {
        float s0 = 0.f, s1 = 0.f;
        #pragma unroll
        for (int ni = 0; ni < 4; ni++)
            #pragma unroll
            for (int q = 0; q < 4; q++) {
                float z = acc[mi][ni][q] + decv[ni * 2 + (q & 1)];
                float t; asm("tanh.approx.f32 %0, %1;" : "=f"(t) : "f"(z));
                float v = t * vwv[ni * 2 + (q & 1)];
                if (q < 2) s0 += v; else s1 += v;
            }
        #pragma unroll
        for (int off = 1; off < 4; off <<= 1) {
            s0 += __shfl_xor_sync(0xffffffffu, s0, off);
            s1 += __shfl_xor_sync(0xffffffffu, s1, off);
        }
        if ((lid & 3) == 0) {
            int ml = wm * 64 + mi * 16 + (lid >> 2);
            part_s[wn * 128 + ml]     = s0;
            part_s[wn * 128 + ml + 8] = s1;
        }
    }
    __syncthreads();
    if (tid < 128) {
        float s = part_s[tid] + part_s[128 + tid] + part_s[256 + tid] + part_s[384 + tid];
        g_part[(size_t)blockIdx.x * MTOT + m0 + tid] = s;
    }
}

// ---------------- kernel 4: masked softmax (512 thr, sums the 4 partials) --
__global__ void softmax_kernel(const int* __restrict__ mask, float* __restrict__ out) {
    int b = blockIdx.x, tid = threadIdx.x;
    const int* mk = mask + (size_t)b * SDIM;
    float v[4], vmax = -3.0e38f;
    #pragma unroll
    for (int i = 0; i < 4; i++) {
        int s = tid + i * 512;
        size_t idx = (size_t)b * SDIM + s;
        float x = g_part[idx] + g_part[MTOT + idx]
                + g_part[2 * MTOT + idx] + g_part[3 * MTOT + idx];
        if (mk[s] == 0) x = -100000.0f;
        v[i] = x; vmax = fmaxf(vmax, x);
    }
    __shared__ float red[16], red2[16];
    #pragma unroll
    for (int o = 16; o > 0; o >>= 1) vmax = fmaxf(vmax, __shfl_xor_sync(0xffffffffu, vmax, o));
    if ((tid & 31) == 0) red[tid >> 5] = vmax;
    __syncthreads();
    if (tid == 0) { float m = red[0]; for (int i = 1; i < 16; i++) m = fmaxf(m, red[i]); red[0] = m; }
    __syncthreads();
    float m = red[0], sum = 0.f;
    #pragma unroll
    for (int i = 0; i < 4; i++) { v[i] = expf(v[i] - m); sum += v[i]; }
    #pragma unroll
    for (int o = 16; o > 0; o >>= 1) sum += __shfl_xor_sync(0xffffffffu, sum, o);
    if ((tid & 31) == 0) red2[tid >> 5] = sum;
    __syncthreads();
    if (tid == 0) { float s = 0.f; for (int i = 0; i < 16; i++) s += red2[i]; red2[0] = s; }
    __syncthreads();
    float inv = 1.0f / red2[0];
    #pragma unroll
    for (int i = 0; i < 4; i++) out[(size_t)b * SDIM + tid + i * 512] = v[i] * inv;
}

// ---------------- launch ----------------
extern "C" void kernel_launch(void* const* d_in, const int* in_sizes, int n_in,
                              void* d_out, int out_size) {
    const float* decoder_hide = (const float*)d_in[0];
    const float* encoder_out  = (const float*)d_in[1];
    const int*   mask         = (const int*)d_in[2];
    const float* W_attn       = (const float*)d_in[3];
    const float* b_attn       = (const float*)d_in[4];
    const float* v_w          = (const float*)d_in[5];
    float* out = (float*)d_out;

    cudaFuncSetAttribute(gemm_kernel, cudaFuncAttributeMaxDynamicSharedMemorySize, SMEM_TOTAL);

    prep_all<<<1024, dim3(32, 8)>>>(W_attn, decoder_hide, b_attn);
    gemm_kernel<<<dim3(NSPLIT, NTILES), 256, SMEM_TOTAL>>>(encoder_out, v_w);
    softmax_kernel<<<BATCH, 512>>>(mask, out);
}

// round 17
// speedup vs baseline: 1.4772x; 1.4772x over previous
#include <cuda_runtime.h>
#include <cuda_fp16.h>
#include <cstdint>

#define H      512
#define SDIM   2048
#define BATCH  32
#define KDIM   1024      // 2*H
#define MTOT   65536     // BATCH*SDIM
#define M_TILE 128
#define N_TILE 128
#define K_TILE 64        // fp16 elems per k-tile = 128 B rows
#define NKT    16        // KDIM / K_TILE
#define NSTAGE 3
#define NSPLIT 4         // H / N_TILE
#define NTILES (MTOT / M_TILE)   // 512

// ---------------- scratch (device globals: allocation-free) ----------------
__device__ __half g_ench[(size_t)MTOT * KDIM];   // encoder_out in fp16 (128 MB)
__device__ __half g_Wth[H * KDIM];               // W_e^T [n][k] in fp16
__device__ float  g_dec[BATCH * H];              // dec_proj + b_attn (fp32 exact)
__device__ float  g_part[NSPLIT * MTOT];         // per-N-slice partial logits
__device__ int    g_flag[NTILES * 4];            // per-(m-tile, k-slice) ready flags

#define STAGE_BYTES 16384
#define B_BASE      (NSTAGE * STAGE_BYTES)
#define SMEM_TOTAL  (2 * NSTAGE * STAGE_BYTES)   // 96 KB

__device__ __forceinline__ uint32_t smem_u32(const void* p) {
    uint32_t a;
    asm("{ .reg .u64 t; cvta.to.shared.u64 t, %1; cvt.u32.u64 %0, t; }" : "=r"(a) : "l"(p));
    return a;
}
__device__ __forceinline__ uint32_t h2_bits(__half2 h) {
    return *reinterpret_cast<uint32_t*>(&h);
}
__device__ __forceinline__ void cp16(uint32_t dst, const void* src) {
    asm volatile("cp.async.cg.shared.global [%0], [%1], 16;" :: "r"(dst), "l"(src) : "memory");
}
__device__ __forceinline__ void ldsm4(uint32_t* r, uint32_t addr) {
    asm volatile("ldmatrix.sync.aligned.m8n8.x4.shared.b16 {%0,%1,%2,%3}, [%4];"
                 : "=r"(r[0]), "=r"(r[1]), "=r"(r[2]), "=r"(r[3]) : "r"(addr));
}
__device__ __forceinline__ void mma_f16(float* c, const uint32_t* a, uint32_t b0, uint32_t b1) {
    asm volatile(
        "mma.sync.aligned.m16n8k16.row.col.f32.f16.f16.f32 "
        "{%0,%1,%2,%3}, {%4,%5,%6,%7}, {%8,%9}, {%0,%1,%2,%3};"
        : "+f"(c[0]), "+f"(c[1]), "+f"(c[2]), "+f"(c[3])
        : "r"(a[0]), "r"(a[1]), "r"(a[2]), "r"(a[3]), "r"(b0), "r"(b1));
}

// ---------------- kernel 1: W_e transpose + fp16 round, + zero flags -------
__global__ void prep_w(const float* __restrict__ W) {
    __shared__ float tile[32][33];
    int kb = blockIdx.x * 32, nb = blockIdx.y * 32;
    int tx = threadIdx.x, ty = threadIdx.y;
    if (tx < 4 && ty == 0)
        g_flag[(blockIdx.y * 32 + blockIdx.x) * 4 + tx] = 0;   // 512 blocks x 4
    #pragma unroll
    for (int i = ty; i < 32; i += 8)
        tile[i][tx] = W[(size_t)(H + kb + i) * H + nb + tx];
    __syncthreads();
    #pragma unroll
    for (int i = ty; i < 32; i += 8)
        g_Wth[(size_t)(nb + i) * KDIM + kb + tx] = __float2half_rn(tile[tx][i]);
}

// ---------------- kernel 2: dec_proj = decoder_hide @ W_h + b_attn ---------
__global__ void prep_dec(const float* __restrict__ dh,
                         const float* __restrict__ W,
                         const float* __restrict__ bias) {
    __shared__ float row[H];
    __shared__ float red[8][32];
    int b = blockIdx.y;
    int h = blockIdx.x * 32 + threadIdx.x;
    int tx = threadIdx.x, ty = threadIdx.y;
    for (int i = ty * 32 + tx; i < H; i += 256) row[i] = dh[b * H + i];
    __syncthreads();
    float acc = 0.f;
    #pragma unroll 8
    for (int kk = 0; kk < 64; kk++) {
        int k = ty * 64 + kk;
        acc = fmaf(row[k], W[(size_t)k * H + h], acc);
    }
    red[ty][tx] = acc;
    __syncthreads();
    if (ty == 0) {
        float s = bias[h];
        #pragma unroll
        for (int j = 0; j < 8; j++) s += red[j][tx];
        g_dec[b * H + h] = s;
    }
}

// ---------------- kernel 3: fused convert + fp16 GEMM + tanh + v_w reduce --
// grid (NSPLIT, NTILES). CTA (x,y) converts K-slice x of A tile y FIRST (no
// cp.asyncs outstanding -> clean publish), releases a flag, then runs the
// K-mainloop ROTATED to start at its own slice (kt = 4x). Foreign-slice
// acquire waits are expected pre-satisfied. Publish relies on __syncthreads
// (intra-CTA HB) + release store; consumer pairs with acquire load.
__global__ void __launch_bounds__(256, 2)
gemm_kernel(const float* __restrict__ enc, const float* __restrict__ vw) {
    extern __shared__ char smem[];
    const uint32_t sbase = smem_u32(smem);
    const int tid = threadIdx.x, lid = tid & 31, wid = tid >> 5;
    const int wm = wid & 1, wn = wid >> 1;          // 2 x 4 warp grid
    const int m0 = blockIdx.y * M_TILE;
    const int nb = blockIdx.x * N_TILE;
    const int batch = blockIdx.y >> 4;              // 16 M-tiles per batch row
    const int xs = blockIdx.x;                      // this CTA's K-slice
    const int x4 = xs * 4;                          // first kt of own slice

    // ---- convert K-slice xs of tile y: cols [xs*256, +256) of 128 rows -----
    {
        const float4* s4 = (const float4*)(enc + (size_t)m0 * KDIM + xs * 256);
        uint2* d2 = (uint2*)(g_ench + (size_t)m0 * KDIM + xs * 256);
        #pragma unroll 8
        for (int j = 0; j < 32; j++) {               // 128 rows * 64 f4 / 256 thr
            int c = tid + j * 256;
            int r = c >> 6, c4 = c & 63;             // 64 float4 per row-slice
            float4 f = s4[(size_t)r * 256 + c4];     // row stride KDIM/4 f4
            uint2 o;
            o.x = h2_bits(__floats2half2_rn(f.x, f.y));
            o.y = h2_bits(__floats2half2_rn(f.z, f.w));
            d2[(size_t)r * 256 + c4] = o;            // row stride KDIM/2 uint2
        }
        __syncthreads();                             // intra-CTA HB for all stores
        if (tid == 0)
            asm volatile("st.global.release.gpu.b32 [%0], %1;"
                         :: "l"(&g_flag[blockIdx.y * 4 + xs]), "r"(1) : "memory");
    }

    const int s7 = lid & 7;
    const int rA = s7 + 8 * ((lid >> 3) & 1);       // A ldsm row-in-16
    const int cA = (lid >> 4) & 1;                  // A chunk parity (k8)
    const int rB = s7 + 8 * ((lid >> 4) & 1);       // B ldsm row-in-16
    const int cB = (lid >> 3) & 1;                  // B chunk parity

    float acc[4][4][4];
    #pragma unroll
    for (int mi = 0; mi < 4; mi++)
        #pragma unroll
        for (int ni = 0; ni < 4; ni++)
            #pragma unroll
            for (int q = 0; q < 4; q++) acc[mi][ni][q] = 0.f;

    auto load_stage = [&](int slot, int kt) {
        const __half* asrc = g_ench + (size_t)m0 * KDIM + kt * K_TILE;
        uint32_t abase = sbase + slot * STAGE_BYTES;
        #pragma unroll
        for (int i = 0; i < 4; i++) {
            int c = tid + i * 256;
            int row = c >> 3, cu = c & 7;
            cp16(abase + row * 128 + ((cu ^ (row & 7)) << 4),
                 asrc + (size_t)row * KDIM + cu * 8);
        }
        const __half* bsrc = g_Wth + (size_t)nb * KDIM + kt * K_TILE;
        uint32_t bbase = sbase + B_BASE + slot * STAGE_BYTES;
        #pragma unroll
        for (int i = 0; i < 4; i++) {
            int c = tid + i * 256;
            int row = c >> 3, cu = c & 7;
            cp16(bbase + row * 128 + ((cu ^ (row & 7)) << 4),
                 bsrc + (size_t)row * KDIM + cu * 8);
        }
    };

    auto wait_slice = [&](int s) {                   // all threads spin; bcast addr
        const int* fp = &g_flag[blockIdx.y * 4 + s];
        int v;
        do {
            asm volatile("ld.global.acquire.gpu.b32 %0, [%1];"
                         : "=r"(v) : "l"(fp) : "memory");
            if (!v) __nanosleep(50);
        } while (!v);
    };

    // prologue: own slice, no waits
    load_stage(0, x4);
    asm volatile("cp.async.commit_group;" ::: "memory");
    load_stage(1, (x4 + 1) & 15);
    asm volatile("cp.async.commit_group;" ::: "memory");

    uint32_t aF[2][4][4], bF[2][2][4];

    for (int i = 0; i < NKT; ++i) {
        asm volatile("cp.async.wait_group 1;" ::: "memory");
        __syncthreads();
        if (i + 2 < NKT) {
            const int kta = (x4 + i + 2) & 15;
            if ((kta & 3) == 0 && (kta >> 2) != xs)  // entering a foreign slice
                wait_slice(kta >> 2);
            load_stage((i + 2) % NSTAGE, kta);
        }
        asm volatile("cp.async.commit_group;" ::: "memory");

        const int slot = i % NSTAGE;
        const uint32_t As = sbase + slot * STAGE_BYTES;
        const uint32_t Bs = sbase + B_BASE + slot * STAGE_BYTES;
        uint32_t abA[4], abB[2];
        #pragma unroll
        for (int mi = 0; mi < 4; mi++)
            abA[mi] = As + (wm * 64 + mi * 16 + rA) * 128;
        #pragma unroll
        for (int p = 0; p < 2; p++)
            abB[p] = Bs + (wn * 32 + p * 16 + rB) * 128;

        {
            uint32_t chA = (uint32_t)((cA ^ s7) << 4);
            uint32_t chB = (uint32_t)((cB ^ s7) << 4);
            #pragma unroll
            for (int mi = 0; mi < 4; mi++) ldsm4(aF[0][mi], abA[mi] + chA);
            #pragma unroll
            for (int p = 0; p < 2; p++)    ldsm4(bF[0][p], abB[p] + chB);
        }

        #pragma unroll
        for (int g = 0; g < 4; g++) {                 // k16 groups in k-tile
            const int cur = g & 1, nxt = cur ^ 1;
            if (g < 3) {
                uint32_t chA = (uint32_t)(((2 * (g + 1) + cA) ^ s7) << 4);
                uint32_t chB = (uint32_t)(((2 * (g + 1) + cB) ^ s7) << 4);
                #pragma unroll
                for (int mi = 0; mi < 4; mi++) ldsm4(aF[nxt][mi], abA[mi] + chA);
                #pragma unroll
                for (int p = 0; p < 2; p++)    ldsm4(bF[nxt][p], abB[p] + chB);
            }
            #pragma unroll
            for (int mi = 0; mi < 4; mi++)
                #pragma unroll
                for (int ni = 0; ni < 4; ni++)
                    mma_f16(acc[mi][ni], aF[cur][mi],
                            bF[cur][ni >> 1][(ni & 1) * 2], bF[cur][ni >> 1][(ni & 1) * 2 + 1]);
        }
    }

    // ---------------- epilogue: tanh + v_w reduce across lanes AND wn warps --
    float decv[8], vwv[8];
    #pragma unroll
    for (int ni = 0; ni < 4; ni++)
        #pragma unroll
        for (int j = 0; j < 2; j++) {
            int h = nb + wn * 32 + ni * 8 + 2 * (lid & 3) + j;
            decv[ni * 2 + j] = g_dec[batch * H + h];
            vwv[ni * 2 + j]  = vw[h];
        }
    __syncthreads();                       // stages dead; reuse smem for reduce
    float* part_s = (float*)smem;          // [wn][128] = 2 KB
    #pragma unroll
    for (int mi = 0; mi < 4; mi++) {
        float s0 = 0.f, s1 = 0.f;
        #pragma unroll
        for (int ni = 0; ni < 4; ni++)
            #pragma unroll
            for (int q = 0; q < 4; q++) {
                float z = acc[mi][ni][q] + decv[ni * 2 + (q & 1)];
                float t; asm("tanh.approx.f32 %0, %1;" : "=f"(t) : "f"(z));
                float v = t * vwv[ni * 2 + (q & 1)];
                if (q < 2) s0 += v; else s1 += v;
            }
        #pragma unroll
        for (int off = 1; off < 4; off <<= 1) {
            s0 += __shfl_xor_sync(0xffffffffu, s0, off);
            s1 += __shfl_xor_sync(0xffffffffu, s1, off);
        }
        if ((lid & 3) == 0) {
            int ml = wm * 64 + mi * 16 + (lid >> 2);
            part_s[wn * 128 + ml]     = s0;
            part_s[wn * 128 + ml + 8] = s1;
        }
    }
    __syncthreads();
    if (tid < 128) {
        float s = part_s[tid] + part_s[128 + tid] + part_s[256 + tid] + part_s[384 + tid];
        g_part[(size_t)blockIdx.x * MTOT + m0 + tid] = s;
    }
}

// ---------------- kernel 4: masked softmax (512 thr, sums the 4 partials) --
__global__ void softmax_kernel(const int* __restrict__ mask, float* __restrict__ out) {
    int b = blockIdx.x, tid = threadIdx.x;
    const int* mk = mask + (size_t)b * SDIM;
    float v[4], vmax = -3.0e38f;
    #pragma unroll
    for (int i = 0; i < 4; i++) {
        int s = tid + i * 512;
        size_t idx = (size_t)b * SDIM + s;
        float x = g_part[idx] + g_part[MTOT + idx]
                + g_part[2 * MTOT + idx] + g_part[3 * MTOT + idx];
        if (mk[s] == 0) x = -100000.0f;
        v[i] = x; vmax = fmaxf(vmax, x);
    }
    __shared__ float red[16], red2[16];
    #pragma unroll
    for (int o = 16; o > 0; o >>= 1) vmax = fmaxf(vmax, __shfl_xor_sync(0xffffffffu, vmax, o));
    if ((tid & 31) == 0) red[tid >> 5] = vmax;
    __syncthreads();
    if (tid == 0) { float m = red[0]; for (int i = 1; i < 16; i++) m = fmaxf(m, red[i]); red[0] = m; }
    __syncthreads();
    float m = red[0], sum = 0.f;
    #pragma unroll
    for (int i = 0; i < 4; i++) { v[i] = expf(v[i] - m); sum += v[i]; }
    #pragma unroll
    for (int o = 16; o > 0; o >>= 1) sum += __shfl_xor_sync(0xffffffffu, sum, o);
    if ((tid & 31) == 0) red2[tid >> 5] = sum;
    __syncthreads();
    if (tid == 0) { float s = 0.f; for (int i = 0; i < 16; i++) s += red2[i]; red2[0] = s; }
    __syncthreads();
    float inv = 1.0f / red2[0];
    #pragma unroll
    for (int i = 0; i < 4; i++) out[(size_t)b * SDIM + tid + i * 512] = v[i] * inv;
}

// ---------------- launch ----------------
extern "C" void kernel_launch(void* const* d_in, const int* in_sizes, int n_in,
                              void* d_out, int out_size) {
    const float* decoder_hide = (const float*)d_in[0];
    const float* encoder_out  = (const float*)d_in[1];
    const int*   mask         = (const int*)d_in[2];
    const float* W_attn       = (const float*)d_in[3];
    const float* b_attn       = (const float*)d_in[4];
    const float* v_w          = (const float*)d_in[5];
    float* out = (float*)d_out;

    cudaFuncSetAttribute(gemm_kernel, cudaFuncAttributeMaxDynamicSharedMemorySize, SMEM_TOTAL);

    prep_w<<<dim3(32, 16), dim3(32, 8)>>>(W_attn);
    prep_dec<<<dim3(H / 32, BATCH), dim3(32, 8)>>>(decoder_hide, W_attn, b_attn);
    gemm_kernel<<<dim3(NSPLIT, NTILES), 256, SMEM_TOTAL>>>(encoder_out, v_w);
    softmax_kernel<<<BATCH, 512>>>(mask, out);
}